// round 1
// baseline (speedup 1.0000x reference)
#include <cuda_runtime.h>
#include <cuda_bf16.h>
#include <cstdint>

// Problem constants
constexpr int NN = 50000;
constexpr int EE = 800000;

// ---------------- device scratch (no allocation allowed) ----------------
__device__ int   g_is64;
__device__ int   g_deg[NN];
__device__ int   g_cursor[NN];
__device__ int   g_ptr[NN + 1];
__device__ float g_invdeg[NN];
__device__ int   g_edges[EE];

__device__ float g_agg0[(size_t)NN * 128];
__device__ float g_agg1[(size_t)NN * 128];
__device__ float g_aggm[(size_t)NN * 256];
__device__ float g_h  [(size_t)NN * 256];
__device__ float g_h2 [(size_t)NN * 256];
__device__ float g_pq [(size_t)NN * 128];

// ---------------- edge dtype sniff ----------------
// Node ids < 50000 => if the buffer is int64, every odd int32 word is 0.
// For genuine int32 data, 32 consecutive odd positions all being 0 is ~impossible.
__global__ void sniff_kernel(const int* __restrict__ e32) {
    int is64 = 1;
    for (int i = 1; i < 64; i += 2) {
        if (e32[i] != 0) { is64 = 0; break; }
    }
    g_is64 = is64;
}

__device__ __forceinline__ int load_edge(const void* e, int idx) {
    if (g_is64) return (int)((const long long*)e)[idx];
    return ((const int*)e)[idx];
}

// ---------------- CSR build ----------------
__global__ void zero_kernel() {
    int i = blockIdx.x * blockDim.x + threadIdx.x;
    if (i < NN) { g_deg[i] = 0; g_cursor[i] = 0; }
}

__global__ void deg_kernel(const void* __restrict__ e) {
    int i = blockIdx.x * blockDim.x + threadIdx.x;
    if (i >= EE) return;
    int dst = load_edge(e, EE + i);
    atomicAdd(&g_deg[dst], 1);
}

__global__ void scan_kernel() {
    constexpr int T = 1024;
    constexpr int CHUNK = (NN + T - 1) / T;
    __shared__ int ssum[T];
    int t = threadIdx.x;
    int lo = t * CHUNK;
    int hi = min(lo + CHUNK, NN);
    int s = 0;
    for (int i = lo; i < hi; i++) s += g_deg[i];
    ssum[t] = s;
    __syncthreads();
    // Hillis-Steele inclusive scan
    for (int off = 1; off < T; off <<= 1) {
        int v = (t >= off) ? ssum[t - off] : 0;
        __syncthreads();
        if (t >= off) ssum[t] += v;
        __syncthreads();
    }
    int run = (t == 0) ? 0 : ssum[t - 1];
    for (int i = lo; i < hi; i++) {
        g_ptr[i] = run;
        int d = g_deg[i];
        run += d;
        g_invdeg[i] = 1.0f / (float)max(d, 1);
    }
    if (t == 0) g_ptr[NN] = EE;
}

__global__ void scatter_kernel(const void* __restrict__ e) {
    int i = blockIdx.x * blockDim.x + threadIdx.x;
    if (i >= EE) return;
    int src = load_edge(e, i);
    int dst = load_edge(e, EE + i);
    int pos = g_ptr[dst] + atomicAdd(&g_cursor[dst], 1);
    g_edges[pos] = src;
}

// ---------------- mean aggregation: one block per dst node ----------------
__global__ void agg_kernel(const float* __restrict__ X, int ldx,
                           float* __restrict__ O, int ldo) {
    int node = blockIdx.x;
    int t = threadIdx.x;
    int s = g_ptr[node], e = g_ptr[node + 1];
    float acc = 0.f;
    for (int i = s; i < e; i++) {
        int src = g_edges[i];
        acc += __ldg(X + (size_t)src * ldx + t);
    }
    O[(size_t)node * ldo + t] = acc * g_invdeg[node];
}

// final layer: out = mean_agg(P) + Q where PQ = [P | Q], P = h2@Wlo, Q = h2@Wro + bo
__global__ void final_kernel(float* __restrict__ out) {
    int node = blockIdx.x;
    int t = threadIdx.x;  // 0..63
    int s = g_ptr[node], e = g_ptr[node + 1];
    float acc = 0.f;
    for (int i = s; i < e; i++) {
        int src = g_edges[i];
        acc += __ldg(&g_pq[(size_t)src * 128 + t]);
    }
    out[(size_t)node * 64 + t] = acc * g_invdeg[node] + g_pq[(size_t)node * 128 + 64 + t];
}

// ---------------- fused dual GEMM: C = A1@W1 + A2@W2 + b (opt relu) ----------------
// A1, A2: [NN, K] (row strides lda1/lda2). W1, W2: [K, M] row-major.
// C: [NN, M-slice] with row stride ldc. A2 may be null (single GEMM).
#define BM 128
#define BN 128
#define BKK 8

__global__ __launch_bounds__(256) void gemm_kernel(
    const float* __restrict__ A1, int lda1,
    const float* __restrict__ A2, int lda2,
    const float* __restrict__ W1, const float* __restrict__ W2,
    int K, int M,
    const float* __restrict__ bias,
    float* __restrict__ C, int ldc,
    int relu)
{
    __shared__ float As[BKK][132];
    __shared__ float Bs[BKK][132];

    int tid = threadIdx.x;
    int tx = tid & 15;    // n dimension
    int ty = tid >> 4;    // m dimension
    int row0 = blockIdx.x * BM;
    int col0 = blockIdx.y * BN;

    float acc[8][8];
#pragma unroll
    for (int i = 0; i < 8; i++)
#pragma unroll
        for (int j = 0; j < 8; j++) acc[i][j] = 0.f;

    int Ktot = (A2 != nullptr) ? 2 * K : K;

    for (int kt = 0; kt < Ktot; kt += BKK) {
        const float* A; int lda; int kb; const float* W;
        if (kt < K) { A = A1; lda = lda1; W = W1; kb = kt; }
        else        { A = A2; lda = lda2; W = W2; kb = kt - K; }

        // Load A tile 128x8 (transposed into As[k][m])
        {
            int r = tid >> 1;            // 0..127
            int c = (tid & 1) * 4;       // 0 or 4
            int grow = row0 + r;
            float4 v = make_float4(0.f, 0.f, 0.f, 0.f);
            if (grow < NN)
                v = *(const float4*)(A + (size_t)grow * lda + kb + c);
            As[c + 0][r] = v.x;
            As[c + 1][r] = v.y;
            As[c + 2][r] = v.z;
            As[c + 3][r] = v.w;
        }
        // Load B tile 8x128
        {
            int kk = tid >> 5;            // 0..7
            int n  = (tid & 31) * 4;      // 0..124
            int gcol = col0 + n;
            float4 w = make_float4(0.f, 0.f, 0.f, 0.f);
            if (gcol < M)
                w = *(const float4*)(W + (size_t)(kb + kk) * M + gcol);
            *(float4*)&Bs[kk][n] = w;
        }
        __syncthreads();

#pragma unroll
        for (int kk = 0; kk < BKK; kk++) {
            float a[8], b[8];
            *(float4*)&a[0] = *(const float4*)&As[kk][ty * 8];
            *(float4*)&a[4] = *(const float4*)&As[kk][ty * 8 + 4];
            *(float4*)&b[0] = *(const float4*)&Bs[kk][tx * 8];
            *(float4*)&b[4] = *(const float4*)&Bs[kk][tx * 8 + 4];
#pragma unroll
            for (int i = 0; i < 8; i++)
#pragma unroll
                for (int j = 0; j < 8; j++)
                    acc[i][j] = fmaf(a[i], b[j], acc[i][j]);
        }
        __syncthreads();
    }

#pragma unroll
    for (int i = 0; i < 8; i++) {
        int r = row0 + ty * 8 + i;
        if (r >= NN) continue;
#pragma unroll
        for (int j = 0; j < 8; j++) {
            int c = col0 + tx * 8 + j;
            if (c >= M) continue;
            float v = acc[i][j];
            if (bias) v += bias[c];
            if (relu) v = fmaxf(v, 0.f);
            C[(size_t)r * ldc + c] = v;
        }
    }
}

// ---------------- launch ----------------
extern "C" void kernel_launch(void* const* d_in, const int* in_sizes, int n_in,
                              void* d_out, int out_size) {
    const float* x0  = (const float*)d_in[0];
    const float* x1  = (const float*)d_in[1];
    const void*  eix = d_in[2];
    const float* Wl0 = (const float*)d_in[3];
    const float* Wr0 = (const float*)d_in[4];
    const float* b0  = (const float*)d_in[5];
    const float* Wl1 = (const float*)d_in[6];
    const float* Wr1 = (const float*)d_in[7];
    const float* b1  = (const float*)d_in[8];
    const float* Wlm = (const float*)d_in[9];
    const float* Wrm = (const float*)d_in[10];
    const float* bm  = (const float*)d_in[11];
    const float* Wlo = (const float*)d_in[12];
    const float* Wro = (const float*)d_in[13];
    const float* bo  = (const float*)d_in[14];
    float* out = (float*)d_out;

    float *agg0, *agg1, *aggm, *h, *h2, *pq;
    cudaGetSymbolAddress((void**)&agg0, g_agg0);
    cudaGetSymbolAddress((void**)&agg1, g_agg1);
    cudaGetSymbolAddress((void**)&aggm, g_aggm);
    cudaGetSymbolAddress((void**)&h,    g_h);
    cudaGetSymbolAddress((void**)&h2,   g_h2);
    cudaGetSymbolAddress((void**)&pq,   g_pq);

    // CSR build
    sniff_kernel<<<1, 1>>>((const int*)eix);
    zero_kernel<<<(NN + 255) / 256, 256>>>();
    deg_kernel<<<(EE + 255) / 256, 256>>>(eix);
    scan_kernel<<<1, 1024>>>();
    scatter_kernel<<<(EE + 255) / 256, 256>>>(eix);

    const int GX = (NN + BM - 1) / BM;  // 391

    // Layer 0 + 1 (branch convs) -> h = [relu(sage0) | relu(sage1)]
    agg_kernel<<<NN, 128>>>(x0, 128, agg0, 128);
    agg_kernel<<<NN, 128>>>(x1, 128, agg1, 128);
    gemm_kernel<<<dim3(GX, 1), 256>>>(agg0, 128, x0, 128, Wl0, Wr0, 128, 128, b0, h,       256, 1);
    gemm_kernel<<<dim3(GX, 1), 256>>>(agg1, 128, x1, 128, Wl1, Wr1, 128, 128, b1, h + 128, 256, 1);

    // Middle conv: h2 = relu(agg(h)@Wlm + h@Wrm + bm)
    agg_kernel<<<NN, 256>>>(h, 256, aggm, 256);
    gemm_kernel<<<dim3(GX, 2), 256>>>(aggm, 256, h, 256, Wlm, Wrm, 256, 256, bm, h2, 256, 1);

    // Final conv: exploit linearity — project first, aggregate 64-d after.
    // pq = [ h2@Wlo | h2@Wro + bo ]
    gemm_kernel<<<dim3(GX, 1), 256>>>(h2, 256, nullptr, 0, Wlo, nullptr, 256, 64, nullptr, pq,      128, 0);
    gemm_kernel<<<dim3(GX, 1), 256>>>(h2, 256, nullptr, 0, Wro, nullptr, 256, 64, bo,      pq + 64, 128, 0);
    // out = mean_agg(P) + Q
    final_kernel<<<NN, 64>>>(out);
}

// round 4
// speedup vs baseline: 2.1333x; 2.1333x over previous
#include <cuda_runtime.h>
#include <cuda_bf16.h>
#include <cstdint>

// Problem constants
constexpr int NN = 50000;
constexpr int EE = 800000;
constexpr int KC = 64;          // K-chunk (bf16 elems) per SMEM stage
constexpr int SCANB = 49;       // ceil(NN/1024)

// ---------------- device scratch (no allocation allowed) ----------------
__device__ int   g_is64;
__device__ int   g_deg[NN];
__device__ int   g_cursor[NN];
__device__ int   g_ptr[NN + 1];
__device__ float g_invdeg[NN];
__device__ int   g_edges[EE];
__device__ int   g_part[SCANB];
__device__ int   g_boff[SCANB];

// bf16 hi/lo planes for all activations
__device__ __nv_bfloat16 g_xh0[(size_t)NN * 128];
__device__ __nv_bfloat16 g_xl0[(size_t)NN * 128];
__device__ __nv_bfloat16 g_xh1[(size_t)NN * 128];
__device__ __nv_bfloat16 g_xl1[(size_t)NN * 128];
__device__ __nv_bfloat16 g_a0h[(size_t)NN * 128];
__device__ __nv_bfloat16 g_a0l[(size_t)NN * 128];
__device__ __nv_bfloat16 g_a1h[(size_t)NN * 128];
__device__ __nv_bfloat16 g_a1l[(size_t)NN * 128];
__device__ __nv_bfloat16 g_hh [(size_t)NN * 256];
__device__ __nv_bfloat16 g_hl [(size_t)NN * 256];
__device__ __nv_bfloat16 g_amh[(size_t)NN * 256];
__device__ __nv_bfloat16 g_aml[(size_t)NN * 256];
__device__ __nv_bfloat16 g_h2h[(size_t)NN * 256];
__device__ __nv_bfloat16 g_h2l[(size_t)NN * 256];
__device__ float         g_pq [(size_t)NN * 128];

// transposed + split weights: WT[n][k] = W[k][n], combined over Ktot
__device__ __nv_bfloat16 g_WT0h[128 * 256];
__device__ __nv_bfloat16 g_WT0l[128 * 256];
__device__ __nv_bfloat16 g_WT1h[128 * 256];
__device__ __nv_bfloat16 g_WT1l[128 * 256];
__device__ __nv_bfloat16 g_WTmh[256 * 512];
__device__ __nv_bfloat16 g_WTml[256 * 512];
__device__ __nv_bfloat16 g_WTfh[128 * 256];
__device__ __nv_bfloat16 g_WTfl[128 * 256];
__device__ float         g_biasf[128];

// ---------------- edge dtype sniff ----------------
__global__ void sniff_kernel(const int* __restrict__ e32) {
    int is64 = 1;
    for (int i = 1; i < 64; i += 2)
        if (e32[i] != 0) { is64 = 0; break; }
    g_is64 = is64;
}
__device__ __forceinline__ int load_edge(const void* e, int idx) {
    if (g_is64) return (int)((const long long*)e)[idx];
    return ((const int*)e)[idx];
}

// ---------------- CSR build ----------------
__global__ void zero_kernel() {
    int i = blockIdx.x * blockDim.x + threadIdx.x;
    if (i < NN) { g_deg[i] = 0; g_cursor[i] = 0; }
}
__global__ void deg_kernel(const void* __restrict__ e) {
    int i = blockIdx.x * blockDim.x + threadIdx.x;
    if (i >= EE) return;
    atomicAdd(&g_deg[load_edge(e, EE + i)], 1);
}
__global__ void scan1_kernel() {
    __shared__ int sm[1024];
    int t = threadIdx.x;
    int i = blockIdx.x * 1024 + t;
    sm[t] = (i < NN) ? g_deg[i] : 0;
    __syncthreads();
    for (int off = 512; off; off >>= 1) {
        if (t < off) sm[t] += sm[t + off];
        __syncthreads();
    }
    if (t == 0) g_part[blockIdx.x] = sm[0];
}
__global__ void scan2_kernel() {
    if (threadIdx.x == 0) {
        int run = 0;
        for (int b = 0; b < SCANB; b++) { g_boff[b] = run; run += g_part[b]; }
        g_ptr[NN] = EE;
    }
}
__global__ void scan3_kernel() {
    __shared__ int sm[1024];
    int t = threadIdx.x;
    int i = blockIdx.x * 1024 + t;
    int v = (i < NN) ? g_deg[i] : 0;
    sm[t] = v;
    __syncthreads();
    for (int off = 1; off < 1024; off <<= 1) {
        int u = (t >= off) ? sm[t - off] : 0;
        __syncthreads();
        if (t >= off) sm[t] += u;
        __syncthreads();
    }
    if (i < NN) {
        g_ptr[i] = g_boff[blockIdx.x] + sm[t] - v;
        g_invdeg[i] = 1.0f / (float)max(v, 1);
    }
}
__global__ void scatter_kernel(const void* __restrict__ e) {
    int i = blockIdx.x * blockDim.x + threadIdx.x;
    if (i >= EE) return;
    int src = load_edge(e, i);
    int dst = load_edge(e, EE + i);
    g_edges[g_ptr[dst] + atomicAdd(&g_cursor[dst], 1)] = src;
}

// ---------------- bf16 split helpers ----------------
__device__ __forceinline__ void split2(float v, __nv_bfloat16& h, __nv_bfloat16& l) {
    h = __float2bfloat16(v);
    l = __float2bfloat16(v - __bfloat162float(h));
}

__global__ void convert_kernel(const float* __restrict__ x0, const float* __restrict__ x1) {
    size_t i = (size_t)blockIdx.x * blockDim.x + threadIdx.x;
    if (i >= (size_t)NN * 128) return;
    split2(x0[i], g_xh0[i], g_xl0[i]);
    split2(x1[i], g_xh1[i], g_xl1[i]);
}

__global__ void wprep_kernel(const float* __restrict__ Wl0, const float* __restrict__ Wr0,
                             const float* __restrict__ Wl1, const float* __restrict__ Wr1,
                             const float* __restrict__ Wlm, const float* __restrict__ Wrm,
                             const float* __restrict__ Wlo, const float* __restrict__ Wro,
                             const float* __restrict__ bo) {
    int i = blockIdx.x * blockDim.x + threadIdx.x;
    if (i < 128 * 256) {
        int n = i >> 8, k = i & 255;
        float w0 = (k < 128) ? Wl0[k * 128 + n] : Wr0[(k - 128) * 128 + n];
        float w1 = (k < 128) ? Wl1[k * 128 + n] : Wr1[(k - 128) * 128 + n];
        split2(w0, g_WT0h[i], g_WT0l[i]);
        split2(w1, g_WT1h[i], g_WT1l[i]);
        float wf = (n < 64) ? Wlo[k * 64 + n] : Wro[k * 64 + (n - 64)];
        split2(wf, g_WTfh[i], g_WTfl[i]);
        if (i < 128) g_biasf[i] = (i < 64) ? 0.f : bo[i - 64];
    }
    int j = i - 128 * 256;
    if (j >= 0 && j < 256 * 512) {
        int n = j >> 9, k = j & 511;
        float w = (k < 256) ? Wlm[k * 256 + n] : Wrm[(k - 256) * 256 + n];
        split2(w, g_WTmh[j], g_WTml[j]);
    }
}

// ---------------- aggregation ----------------
__global__ void agg_f32_planes(const float* __restrict__ X,
                               __nv_bfloat16* __restrict__ Oh, __nv_bfloat16* __restrict__ Ol) {
    int node = blockIdx.x;
    int t = threadIdx.x; // 128
    int s = g_ptr[node], e = g_ptr[node + 1];
    float acc = 0.f;
    for (int i = s; i < e; i++)
        acc += __ldg(X + (size_t)g_edges[i] * 128 + t);
    acc *= g_invdeg[node];
    split2(acc, Oh[(size_t)node * 128 + t], Ol[(size_t)node * 128 + t]);
}

__global__ void agg_planes(const __nv_bfloat16* __restrict__ Xh, const __nv_bfloat16* __restrict__ Xl,
                           __nv_bfloat16* __restrict__ Oh, __nv_bfloat16* __restrict__ Ol) {
    int node = blockIdx.x;
    int t = threadIdx.x; // 256
    int s = g_ptr[node], e = g_ptr[node + 1];
    float acc = 0.f;
    for (int i = s; i < e; i++) {
        size_t off = (size_t)g_edges[i] * 256 + t;
        acc += __bfloat162float(__ldg(Xh + off)) + __bfloat162float(__ldg(Xl + off));
    }
    acc *= g_invdeg[node];
    split2(acc, Oh[(size_t)node * 256 + t], Ol[(size_t)node * 256 + t]);
}

__global__ void final_kernel(float* __restrict__ out) {
    int node = blockIdx.x;
    int t = threadIdx.x; // 64
    int s = g_ptr[node], e = g_ptr[node + 1];
    float acc = 0.f;
    for (int i = s; i < e; i++)
        acc += __ldg(&g_pq[(size_t)g_edges[i] * 128 + t]);
    out[(size_t)node * 64 + t] = acc * g_invdeg[node] + g_pq[(size_t)node * 128 + 64 + t];
}

// ---------------- mma.sync split-bf16 GEMM ----------------
// C[row, n] = sum_k A[row, k] * WT[n, k] with A = (A1|A2) concat over k.
// fp32 emulated via Ah*Bh + Ah*Bl + Al*Bh with fp32 accumulate.
// CTA: 512 threads = 16 warps in 4x4. CTA tile 128(m) x 128(n). Warp tile 32x32.
// SMEM: Ah/Al/Bh/Bl tiles, 128 rows x 64 cols bf16, padded stride 72 elems (144B)
// so that mma fragment LDS across 8 rows is conflict-free.
#define PAD 72
#define AH_OFF 0
#define AL_OFF (128 * PAD * 2)
#define BH_OFF (2 * 128 * PAD * 2)
#define BL_OFF (3 * 128 * PAD * 2)
#define SMEM_SZ (4 * 128 * PAD * 2)

__device__ __forceinline__ void mma16816(float* d, const uint32_t* a, const uint32_t* b) {
    asm volatile(
        "mma.sync.aligned.m16n8k16.row.col.f32.bf16.bf16.f32 "
        "{%0,%1,%2,%3}, {%4,%5,%6,%7}, {%8,%9}, {%0,%1,%2,%3};"
        : "+f"(d[0]), "+f"(d[1]), "+f"(d[2]), "+f"(d[3])
        : "r"(a[0]), "r"(a[1]), "r"(a[2]), "r"(a[3]), "r"(b[0]), "r"(b[1]));
}

__global__ __launch_bounds__(512) void gemm_mma(
    const __nv_bfloat16* __restrict__ A1h, const __nv_bfloat16* __restrict__ A1l, int lda1,
    const __nv_bfloat16* __restrict__ A2h, const __nv_bfloat16* __restrict__ A2l, int lda2,
    int K1, int Ktot,
    const __nv_bfloat16* __restrict__ WTh, const __nv_bfloat16* __restrict__ WTl,
    const float* __restrict__ bias, int relu,
    __nv_bfloat16* __restrict__ Oh, __nv_bfloat16* __restrict__ Ol,
    float* __restrict__ Of, int ldo, int co)
{
    extern __shared__ char smem[];
    __nv_bfloat16* Ash = (__nv_bfloat16*)(smem + AH_OFF);
    __nv_bfloat16* Asl = (__nv_bfloat16*)(smem + AL_OFF);
    __nv_bfloat16* Bsh = (__nv_bfloat16*)(smem + BH_OFF);
    __nv_bfloat16* Bsl = (__nv_bfloat16*)(smem + BL_OFF);

    int tid = threadIdx.x;
    int wid = tid >> 5;
    int lane = tid & 31;
    int g = lane >> 2, tig = lane & 3;
    int wm = wid >> 2, wn = wid & 3;
    int row0 = blockIdx.x * 128;
    int n0 = blockIdx.y * 128;       // column block of the (possibly wide) output

    const __nv_bfloat16* WThB = WTh + (size_t)n0 * Ktot;
    const __nv_bfloat16* WTlB = WTl + (size_t)n0 * Ktot;

    float acc[2][4][4];
#pragma unroll
    for (int mt = 0; mt < 2; mt++)
#pragma unroll
        for (int nt = 0; nt < 4; nt++)
#pragma unroll
            for (int q = 0; q < 4; q++) acc[mt][nt][q] = 0.f;

    int nchunks = Ktot / KC;
    for (int c = 0; c < nchunks; c++) {
        int kt = c * KC;
        const __nv_bfloat16 *Ah, *Al; int lda, kb;
        if (kt < K1) { Ah = A1h; Al = A1l; lda = lda1; kb = kt; }
        else         { Ah = A2h; Al = A2l; lda = lda2; kb = kt - K1; }

        __syncthreads();
        // A tiles: 128 rows x 64 cols (8 uint4 per row), hi + lo
#pragma unroll
        for (int it = 0; it < 2; it++) {
            int idx = tid + it * 512;          // 0..1023
            int r = idx >> 3, c8 = idx & 7;
            int grow = row0 + r;
            uint4 vh = make_uint4(0, 0, 0, 0), vl = vh;
            if (grow < NN) {
                vh = *(const uint4*)(Ah + (size_t)grow * lda + kb + c8 * 8);
                vl = *(const uint4*)(Al + (size_t)grow * lda + kb + c8 * 8);
            }
            *(uint4*)&Ash[r * PAD + c8 * 8] = vh;
            *(uint4*)&Asl[r * PAD + c8 * 8] = vl;
            // B tiles: rows n0..n0+127 of WT, cols kt..kt+63
            uint4 wh = *(const uint4*)(WThB + (size_t)r * Ktot + kt + c8 * 8);
            uint4 wl = *(const uint4*)(WTlB + (size_t)r * Ktot + kt + c8 * 8);
            *(uint4*)&Bsh[r * PAD + c8 * 8] = wh;
            *(uint4*)&Bsl[r * PAD + c8 * 8] = wl;
        }
        __syncthreads();

#pragma unroll
        for (int ks = 0; ks < KC / 16; ks++) {
            int kk = ks * 16;
            uint32_t ah[2][4], al[2][4];
#pragma unroll
            for (int mt = 0; mt < 2; mt++) {
                int ar = wm * 32 + mt * 16 + g;
                int cA = kk + tig * 2;
                ah[mt][0] = *(const uint32_t*)&Ash[ar * PAD + cA];
                ah[mt][1] = *(const uint32_t*)&Ash[(ar + 8) * PAD + cA];
                ah[mt][2] = *(const uint32_t*)&Ash[ar * PAD + cA + 8];
                ah[mt][3] = *(const uint32_t*)&Ash[(ar + 8) * PAD + cA + 8];
                al[mt][0] = *(const uint32_t*)&Asl[ar * PAD + cA];
                al[mt][1] = *(const uint32_t*)&Asl[(ar + 8) * PAD + cA];
                al[mt][2] = *(const uint32_t*)&Asl[ar * PAD + cA + 8];
                al[mt][3] = *(const uint32_t*)&Asl[(ar + 8) * PAD + cA + 8];
            }
#pragma unroll
            for (int nt = 0; nt < 4; nt++) {
                int bn = wn * 32 + nt * 8 + g;
                int cB = kk + tig * 2;
                uint32_t bh[2], bl[2];
                bh[0] = *(const uint32_t*)&Bsh[bn * PAD + cB];
                bh[1] = *(const uint32_t*)&Bsh[bn * PAD + cB + 8];
                bl[0] = *(const uint32_t*)&Bsl[bn * PAD + cB];
                bl[1] = *(const uint32_t*)&Bsl[bn * PAD + cB + 8];
#pragma unroll
                for (int mt = 0; mt < 2; mt++) {
                    mma16816(acc[mt][nt], ah[mt], bh);
                    mma16816(acc[mt][nt], ah[mt], bl);
                    mma16816(acc[mt][nt], al[mt], bh);
                }
            }
        }
    }

    // epilogue
#pragma unroll
    for (int mt = 0; mt < 2; mt++) {
        int r1 = row0 + wm * 32 + mt * 16 + g;
        int r2 = r1 + 8;
#pragma unroll
        for (int nt = 0; nt < 4; nt++) {
            int cl = wn * 32 + nt * 8 + tig * 2;   // local col in 128-block
            int cg = n0 + cl;                       // global output col
            float b0v = bias[cg], b1v = bias[cg + 1];
            float v00 = acc[mt][nt][0] + b0v, v01 = acc[mt][nt][1] + b1v;
            float v10 = acc[mt][nt][2] + b0v, v11 = acc[mt][nt][3] + b1v;
            if (relu) {
                v00 = fmaxf(v00, 0.f); v01 = fmaxf(v01, 0.f);
                v10 = fmaxf(v10, 0.f); v11 = fmaxf(v11, 0.f);
            }
            if (Of) {
                if (r1 < NN) *(float2*)&Of[(size_t)r1 * ldo + co + cg] = make_float2(v00, v01);
                if (r2 < NN) *(float2*)&Of[(size_t)r2 * ldo + co + cg] = make_float2(v10, v11);
            } else {
                __nv_bfloat162 ph, pl;
                if (r1 < NN) {
                    ph.x = __float2bfloat16(v00); ph.y = __float2bfloat16(v01);
                    pl.x = __float2bfloat16(v00 - __bfloat162float(ph.x));
                    pl.y = __float2bfloat16(v01 - __bfloat162float(ph.y));
                    *(__nv_bfloat162*)&Oh[(size_t)r1 * ldo + co + cg] = ph;
                    *(__nv_bfloat162*)&Ol[(size_t)r1 * ldo + co + cg] = pl;
                }
                if (r2 < NN) {
                    ph.x = __float2bfloat16(v10); ph.y = __float2bfloat16(v11);
                    pl.x = __float2bfloat16(v10 - __bfloat162float(ph.x));
                    pl.y = __float2bfloat16(v11 - __bfloat162float(ph.y));
                    *(__nv_bfloat162*)&Oh[(size_t)r2 * ldo + co + cg] = ph;
                    *(__nv_bfloat162*)&Ol[(size_t)r2 * ldo + co + cg] = pl;
                }
            }
        }
    }
}

// ---------------- launch ----------------
extern "C" void kernel_launch(void* const* d_in, const int* in_sizes, int n_in,
                              void* d_out, int out_size) {
    const float* x0  = (const float*)d_in[0];
    const float* x1  = (const float*)d_in[1];
    const void*  eix = d_in[2];
    const float* Wl0 = (const float*)d_in[3];
    const float* Wr0 = (const float*)d_in[4];
    const float* b0  = (const float*)d_in[5];
    const float* Wl1 = (const float*)d_in[6];
    const float* Wr1 = (const float*)d_in[7];
    const float* b1  = (const float*)d_in[8];
    const float* Wlm = (const float*)d_in[9];
    const float* Wrm = (const float*)d_in[10];
    const float* bm  = (const float*)d_in[11];
    const float* Wlo = (const float*)d_in[12];
    const float* Wro = (const float*)d_in[13];
    const float* bo  = (const float*)d_in[14];
    float* out = (float*)d_out;

    cudaFuncSetAttribute(gemm_mma, cudaFuncAttributeMaxDynamicSharedMemorySize, SMEM_SZ);

    __nv_bfloat16 *xh0, *xl0, *xh1, *xl1, *a0h, *a0l, *a1h, *a1l;
    __nv_bfloat16 *hh, *hl, *amh, *aml, *h2h, *h2l;
    __nv_bfloat16 *WT0h, *WT0l, *WT1h, *WT1l, *WTmh, *WTml, *WTfh, *WTfl;
    float *pq, *biasf;
    cudaGetSymbolAddress((void**)&xh0, g_xh0);  cudaGetSymbolAddress((void**)&xl0, g_xl0);
    cudaGetSymbolAddress((void**)&xh1, g_xh1);  cudaGetSymbolAddress((void**)&xl1, g_xl1);
    cudaGetSymbolAddress((void**)&a0h, g_a0h);  cudaGetSymbolAddress((void**)&a0l, g_a0l);
    cudaGetSymbolAddress((void**)&a1h, g_a1h);  cudaGetSymbolAddress((void**)&a1l, g_a1l);
    cudaGetSymbolAddress((void**)&hh,  g_hh);   cudaGetSymbolAddress((void**)&hl,  g_hl);
    cudaGetSymbolAddress((void**)&amh, g_amh);  cudaGetSymbolAddress((void**)&aml, g_aml);
    cudaGetSymbolAddress((void**)&h2h, g_h2h);  cudaGetSymbolAddress((void**)&h2l, g_h2l);
    cudaGetSymbolAddress((void**)&WT0h, g_WT0h); cudaGetSymbolAddress((void**)&WT0l, g_WT0l);
    cudaGetSymbolAddress((void**)&WT1h, g_WT1h); cudaGetSymbolAddress((void**)&WT1l, g_WT1l);
    cudaGetSymbolAddress((void**)&WTmh, g_WTmh); cudaGetSymbolAddress((void**)&WTml, g_WTml);
    cudaGetSymbolAddress((void**)&WTfh, g_WTfh); cudaGetSymbolAddress((void**)&WTfl, g_WTfl);
    cudaGetSymbolAddress((void**)&pq, g_pq);     cudaGetSymbolAddress((void**)&biasf, g_biasf);

    // CSR build
    sniff_kernel<<<1, 1>>>((const int*)eix);
    zero_kernel<<<(NN + 255) / 256, 256>>>();
    deg_kernel<<<(EE + 255) / 256, 256>>>(eix);
    scan1_kernel<<<SCANB, 1024>>>();
    scan2_kernel<<<1, 32>>>();
    scan3_kernel<<<SCANB, 1024>>>();
    scatter_kernel<<<(EE + 255) / 256, 256>>>(eix);

    // precompute split inputs + weights
    convert_kernel<<<(NN * 128 + 255) / 256, 256>>>(x0, x1);
    wprep_kernel<<<(128 * 256 + 256 * 512 + 255) / 256, 256>>>(Wl0, Wr0, Wl1, Wr1, Wlm, Wrm, Wlo, Wro, bo);

    const int GX = (NN + 127) / 128;  // 391

    // layer 0/1: h[:, :128] and h[:, 128:]
    agg_f32_planes<<<NN, 128>>>(x0, a0h, a0l);
    agg_f32_planes<<<NN, 128>>>(x1, a1h, a1l);
    gemm_mma<<<dim3(GX, 1), 512, SMEM_SZ>>>(a0h, a0l, 128, xh0, xl0, 128, 128, 256,
                                            WT0h, WT0l, b0, 1, hh, hl, nullptr, 256, 0);
    gemm_mma<<<dim3(GX, 1), 512, SMEM_SZ>>>(a1h, a1l, 128, xh1, xl1, 128, 128, 256,
                                            WT1h, WT1l, b1, 1, hh, hl, nullptr, 256, 128);

    // middle conv (N=256 via gridDim.y=2)
    agg_planes<<<NN, 256>>>(hh, hl, amh, aml);
    gemm_mma<<<dim3(GX, 2), 512, SMEM_SZ>>>(amh, aml, 256, hh, hl, 256, 256, 512,
                                            WTmh, WTml, bm, 1, h2h, h2l, nullptr, 256, 0);

    // final conv: pq = h2 @ [Wlo | Wro] (+ biasf), then aggregate 64-d
    gemm_mma<<<dim3(GX, 1), 512, SMEM_SZ>>>(h2h, h2l, 256, h2h, h2l, 256, 256, 256,
                                            WTfh, WTfl, biasf, 0, nullptr, nullptr, pq, 128, 0);
    final_kernel<<<NN, 64>>>(out);
}

// round 7
// speedup vs baseline: 2.8693x; 1.3450x over previous
#include <cuda_runtime.h>
#include <cuda_bf16.h>
#include <cstdint>

constexpr int NN = 50000;
constexpr int EE = 800000;
constexpr int KC = 64;          // K-chunk (elems) per SMEM stage
constexpr int SCANB = 49;       // ceil(NN/1024)

// ---------------- device scratch ----------------
__device__ int   g_is64;
__device__ int   g_deg[NN];
__device__ int   g_cursor[NN];
__device__ int   g_ptr[NN + 1];
__device__ float g_invdeg[NN];
__device__ int   g_edges[EE];
__device__ int   g_part[SCANB];
__device__ int   g_boff[SCANB];

// fp32 activations
__device__ float g_a0f[(size_t)NN * 128];
__device__ float g_a1f[(size_t)NN * 128];
__device__ float g_hf [(size_t)NN * 256];
__device__ float g_amf[(size_t)NN * 256];
__device__ float g_h2f[(size_t)NN * 256];
__device__ float g_pq [(size_t)NN * 128];

// transposed + split weights: WT[n][k] = W[k][n], concat over Ktot
__device__ __nv_bfloat16 g_WT0h[128 * 256];
__device__ __nv_bfloat16 g_WT0l[128 * 256];
__device__ __nv_bfloat16 g_WT1h[128 * 256];
__device__ __nv_bfloat16 g_WT1l[128 * 256];
__device__ __nv_bfloat16 g_WTmh[256 * 512];
__device__ __nv_bfloat16 g_WTml[256 * 512];
__device__ __nv_bfloat16 g_WTfh[128 * 256];
__device__ __nv_bfloat16 g_WTfl[128 * 256];
__device__ float         g_biasf[128];

// ---------------- edge dtype sniff ----------------
__global__ void sniff_kernel(const int* __restrict__ e32) {
    int is64 = 1;
    for (int i = 1; i < 64; i += 2)
        if (e32[i] != 0) { is64 = 0; break; }
    g_is64 = is64;
}
__device__ __forceinline__ int load_edge(const void* e, int idx) {
    if (g_is64) return (int)((const long long*)e)[idx];
    return ((const int*)e)[idx];
}

// ---------------- CSR build ----------------
__global__ void zero_kernel() {
    int i = blockIdx.x * blockDim.x + threadIdx.x;
    if (i < NN) { g_deg[i] = 0; g_cursor[i] = 0; }
}
__global__ void deg_kernel(const void* __restrict__ e) {
    int i = blockIdx.x * blockDim.x + threadIdx.x;
    if (i >= EE) return;
    atomicAdd(&g_deg[load_edge(e, EE + i)], 1);
}
__global__ void scan1_kernel() {
    __shared__ int sm[1024];
    int t = threadIdx.x;
    int i = blockIdx.x * 1024 + t;
    sm[t] = (i < NN) ? g_deg[i] : 0;
    __syncthreads();
    for (int off = 512; off; off >>= 1) {
        if (t < off) sm[t] += sm[t + off];
        __syncthreads();
    }
    if (t == 0) g_part[blockIdx.x] = sm[0];
}
__global__ void scan2_kernel() {
    if (threadIdx.x == 0) {
        int run = 0;
        for (int b = 0; b < SCANB; b++) { g_boff[b] = run; run += g_part[b]; }
        g_ptr[NN] = EE;
    }
}
__global__ void scan3_kernel() {
    __shared__ int sm[1024];
    int t = threadIdx.x;
    int i = blockIdx.x * 1024 + t;
    int v = (i < NN) ? g_deg[i] : 0;
    sm[t] = v;
    __syncthreads();
    for (int off = 1; off < 1024; off <<= 1) {
        int u = (t >= off) ? sm[t - off] : 0;
        __syncthreads();
        if (t >= off) sm[t] += u;
        __syncthreads();
    }
    if (i < NN) {
        g_ptr[i] = g_boff[blockIdx.x] + sm[t] - v;
        g_invdeg[i] = 1.0f / (float)max(v, 1);
    }
}
__global__ void scatter_kernel(const void* __restrict__ e) {
    int i = blockIdx.x * blockDim.x + threadIdx.x;
    if (i >= EE) return;
    int src = load_edge(e, i);
    int dst = load_edge(e, EE + i);
    g_edges[g_ptr[dst] + atomicAdd(&g_cursor[dst], 1)] = src;
}

// ---------------- weight prep ----------------
__device__ __forceinline__ void split2(float v, __nv_bfloat16& h, __nv_bfloat16& l) {
    h = __float2bfloat16(v);
    l = __float2bfloat16(v - __bfloat162float(h));
}
__global__ void wprep_kernel(const float* __restrict__ Wl0, const float* __restrict__ Wr0,
                             const float* __restrict__ Wl1, const float* __restrict__ Wr1,
                             const float* __restrict__ Wlm, const float* __restrict__ Wrm,
                             const float* __restrict__ Wlo, const float* __restrict__ Wro,
                             const float* __restrict__ bo) {
    int i = blockIdx.x * blockDim.x + threadIdx.x;
    if (i < 128 * 256) {
        int n = i >> 8, k = i & 255;
        float w0 = (k < 128) ? Wl0[k * 128 + n] : Wr0[(k - 128) * 128 + n];
        float w1 = (k < 128) ? Wl1[k * 128 + n] : Wr1[(k - 128) * 128 + n];
        split2(w0, g_WT0h[i], g_WT0l[i]);
        split2(w1, g_WT1h[i], g_WT1l[i]);
        float wf = (n < 64) ? Wlo[k * 64 + n] : Wro[k * 64 + (n - 64)];
        split2(wf, g_WTfh[i], g_WTfl[i]);
        if (i < 128) g_biasf[i] = (i < 64) ? 0.f : bo[i - 64];
    }
    int j = i - 128 * 256;
    if (j >= 0 && j < 256 * 512) {
        int n = j >> 9, k = j & 511;
        float w = (k < 256) ? Wlm[k * 256 + n] : Wrm[(k - 256) * 256 + n];
        split2(w, g_WTmh[j], g_WTml[j]);
    }
}

// ---------------- aggregation (vectorized, multi-edge in flight) ----------------
// x0 & x1 together: block 128 = 4 warps; warp w handles edges s+w, s+w+4, ...
// each lane loads one float4 (full 128-f row per warp). SMEM cross-warp reduce.
__global__ __launch_bounds__(128) void agg_xx_kernel(
    const float* __restrict__ x0, const float* __restrict__ x1) {
    __shared__ float red0[4][128];
    __shared__ float red1[4][128];
    int node = blockIdx.x;
    int t = threadIdx.x;
    int lane = t & 31, w = t >> 5;
    int s = g_ptr[node], e = g_ptr[node + 1];
    float4 a0 = make_float4(0.f, 0.f, 0.f, 0.f), a1 = a0;
    for (int i = s + w; i < e; i += 4) {
        int src = g_edges[i];
        float4 v0 = __ldg((const float4*)(x0 + (size_t)src * 128) + lane);
        float4 v1 = __ldg((const float4*)(x1 + (size_t)src * 128) + lane);
        a0.x += v0.x; a0.y += v0.y; a0.z += v0.z; a0.w += v0.w;
        a1.x += v1.x; a1.y += v1.y; a1.z += v1.z; a1.w += v1.w;
    }
    *(float4*)&red0[w][lane * 4] = a0;
    *(float4*)&red1[w][lane * 4] = a1;
    __syncthreads();
    float inv = g_invdeg[node];
    float s0 = (red0[0][t] + red0[1][t]) + (red0[2][t] + red0[3][t]);
    float s1 = (red1[0][t] + red1[1][t]) + (red1[2][t] + red1[3][t]);
    g_a0f[(size_t)node * 128 + t] = s0 * inv;
    g_a1f[(size_t)node * 128 + t] = s1 * inv;
}

// 256-wide agg: block 256 = 8 warps; warp pair (el = w>>1) covers one edge row.
__global__ __launch_bounds__(256) void agg_mid_kernel(const float* __restrict__ X) {
    __shared__ float red[4][256];
    int node = blockIdx.x;
    int t = threadIdx.x;
    int lane = t & 31, w = t >> 5;
    int el = w >> 1, half = w & 1;
    int s = g_ptr[node], e = g_ptr[node + 1];
    float4 a = make_float4(0.f, 0.f, 0.f, 0.f);
    for (int i = s + el; i < e; i += 4) {
        int src = g_edges[i];
        float4 v = __ldg((const float4*)(X + (size_t)src * 256) + half * 32 + lane);
        a.x += v.x; a.y += v.y; a.z += v.z; a.w += v.w;
    }
    *(float4*)&red[el][half * 128 + lane * 4] = a;
    __syncthreads();
    float sum = (red[0][t] + red[1][t]) + (red[2][t] + red[3][t]);
    g_amf[(size_t)node * 256 + t] = sum * g_invdeg[node];
}

// final: out = mean_agg(P) + Q, pq = [P | Q]. block 64 = 4 edge lanes of 16 threads.
__global__ __launch_bounds__(64) void final_kernel(float* __restrict__ out) {
    __shared__ float red[4][64];
    int node = blockIdx.x;
    int t = threadIdx.x;
    int el = t >> 4, c4 = t & 15;
    int s = g_ptr[node], e = g_ptr[node + 1];
    float4 a = make_float4(0.f, 0.f, 0.f, 0.f);
    for (int i = s + el; i < e; i += 4) {
        int src = g_edges[i];
        float4 v = __ldg((const float4*)(g_pq + (size_t)src * 128) + c4);
        a.x += v.x; a.y += v.y; a.z += v.z; a.w += v.w;
    }
    *(float4*)&red[el][c4 * 4] = a;
    __syncthreads();
    float sum = (red[0][t] + red[1][t]) + (red[2][t] + red[3][t]);
    out[(size_t)node * 64 + t] = sum * g_invdeg[node] + g_pq[(size_t)node * 128 + 64 + t];
}

// ---------------- mma.sync split-bf16 GEMM, fp32 A with in-kernel split ----------------
// C[row, n] = sum_k A[row, k] * WT[n, k]; A = (A1|A2) fp32 concat over k.
// fp32 emulated: Ah*Bh + Ah*Bl + Al*Bh, fp32 accumulate.
// 512 threads = 16 warps (4x4); CTA tile 128x128; warp tile 32x32.
// A tile global loads for chunk c+1 are prefetched into registers during chunk c's mma.
#define PAD 72
#define AH_OFF 0
#define AL_OFF (128 * PAD * 2)
#define BH_OFF (2 * 128 * PAD * 2)
#define BL_OFF (3 * 128 * PAD * 2)
#define SMEM_SZ (4 * 128 * PAD * 2)

__device__ __forceinline__ void mma16816(float* d, const uint32_t* a, const uint32_t* b) {
    asm volatile(
        "mma.sync.aligned.m16n8k16.row.col.f32.bf16.bf16.f32 "
        "{%0,%1,%2,%3}, {%4,%5,%6,%7}, {%8,%9}, {%0,%1,%2,%3};"
        : "+f"(d[0]), "+f"(d[1]), "+f"(d[2]), "+f"(d[3])
        : "r"(a[0]), "r"(a[1]), "r"(a[2]), "r"(a[3]), "r"(b[0]), "r"(b[1]));
}

__global__ __launch_bounds__(512) void gemm_mma(
    const float* __restrict__ A1, int lda1,
    const float* __restrict__ A2, int lda2,
    int K1, int Ktot,
    const __nv_bfloat16* __restrict__ WTh, const __nv_bfloat16* __restrict__ WTl,
    const float* __restrict__ bias, int relu,
    float* __restrict__ O, int ldo, int co)
{
    extern __shared__ char smem[];
    __nv_bfloat16* Ash = (__nv_bfloat16*)(smem + AH_OFF);
    __nv_bfloat16* Asl = (__nv_bfloat16*)(smem + AL_OFF);
    __nv_bfloat16* Bsh = (__nv_bfloat16*)(smem + BH_OFF);
    __nv_bfloat16* Bsl = (__nv_bfloat16*)(smem + BL_OFF);

    int tid = threadIdx.x;
    int wid = tid >> 5;
    int lane = tid & 31;
    int g = lane >> 2, tig = lane & 3;
    int wm = wid >> 2, wn = wid & 3;
    int row0 = blockIdx.x * 128;
    int n0 = blockIdx.y * 128;

    const __nv_bfloat16* WThB = WTh + (size_t)n0 * Ktot;
    const __nv_bfloat16* WTlB = WTl + (size_t)n0 * Ktot;

    float acc[2][4][4];
#pragma unroll
    for (int mt = 0; mt < 2; mt++)
#pragma unroll
        for (int nt = 0; nt < 4; nt++)
#pragma unroll
            for (int q = 0; q < 4; q++) acc[mt][nt][q] = 0.f;

    // A-tile prefetch registers: 4 float4 per thread (128 rows x 16 float4/row)
    float4 aReg[4];
    int aRow[4];  // global rows (for bounds)
#pragma unroll
    for (int it = 0; it < 4; it++) {
        int idx = tid + it * 512;
        aRow[it] = row0 + (idx >> 4);
    }

    auto loadA = [&](int c) {
        int kt = c * KC;
        const float* A; int lda, kb;
        if (kt < K1) { A = A1; lda = lda1; kb = kt; }
        else         { A = A2; lda = lda2; kb = kt - K1; }
#pragma unroll
        for (int it = 0; it < 4; it++) {
            int idx = tid + it * 512;
            int c4 = idx & 15;
            float4 v = make_float4(0.f, 0.f, 0.f, 0.f);
            if (aRow[it] < NN)
                v = __ldg((const float4*)(A + (size_t)aRow[it] * lda + kb) + c4);
            aReg[it] = v;
        }
    };

    int nchunks = Ktot / KC;
    loadA(0);
    for (int c = 0; c < nchunks; c++) {
        int kt = c * KC;
        __syncthreads();   // previous chunk's mma done with SMEM
        // store A (split fp32 -> hi/lo bf16)
#pragma unroll
        for (int it = 0; it < 4; it++) {
            int idx = tid + it * 512;
            int r = idx >> 4, c4 = idx & 15;
            float4 v = aReg[it];
            __nv_bfloat162 h01, h23, l01, l23;
            h01.x = __float2bfloat16(v.x); l01.x = __float2bfloat16(v.x - __bfloat162float(h01.x));
            h01.y = __float2bfloat16(v.y); l01.y = __float2bfloat16(v.y - __bfloat162float(h01.y));
            h23.x = __float2bfloat16(v.z); l23.x = __float2bfloat16(v.z - __bfloat162float(h23.x));
            h23.y = __float2bfloat16(v.w); l23.y = __float2bfloat16(v.w - __bfloat162float(h23.y));
            uint2 uh, ul;
            uh.x = *(uint32_t*)&h01; uh.y = *(uint32_t*)&h23;
            ul.x = *(uint32_t*)&l01; ul.y = *(uint32_t*)&l23;
            *(uint2*)&Ash[r * PAD + c4 * 4] = uh;
            *(uint2*)&Asl[r * PAD + c4 * 4] = ul;
        }
        // store B (pre-split planes, straight copy)
#pragma unroll
        for (int it = 0; it < 2; it++) {
            int idx = tid + it * 512;
            int r = idx >> 3, c8 = idx & 7;
            uint4 wh = *(const uint4*)(WThB + (size_t)r * Ktot + kt + c8 * 8);
            uint4 wl = *(const uint4*)(WTlB + (size_t)r * Ktot + kt + c8 * 8);
            *(uint4*)&Bsh[r * PAD + c8 * 8] = wh;
            *(uint4*)&Bsl[r * PAD + c8 * 8] = wl;
        }
        __syncthreads();
        if (c + 1 < nchunks) loadA(c + 1);  // overlap next A loads with mma

#pragma unroll
        for (int ks = 0; ks < KC / 16; ks++) {
            int kk = ks * 16;
            uint32_t ah[2][4], al[2][4];
#pragma unroll
            for (int mt = 0; mt < 2; mt++) {
                int ar = wm * 32 + mt * 16 + g;
                int cA = kk + tig * 2;
                ah[mt][0] = *(const uint32_t*)&Ash[ar * PAD + cA];
                ah[mt][1] = *(const uint32_t*)&Ash[(ar + 8) * PAD + cA];
                ah[mt][2] = *(const uint32_t*)&Ash[ar * PAD + cA + 8];
                ah[mt][3] = *(const uint32_t*)&Ash[(ar + 8) * PAD + cA + 8];
                al[mt][0] = *(const uint32_t*)&Asl[ar * PAD + cA];
                al[mt][1] = *(const uint32_t*)&Asl[(ar + 8) * PAD + cA];
                al[mt][2] = *(const uint32_t*)&Asl[ar * PAD + cA + 8];
                al[mt][3] = *(const uint32_t*)&Asl[(ar + 8) * PAD + cA + 8];
            }
#pragma unroll
            for (int nt = 0; nt < 4; nt++) {
                int bn = wn * 32 + nt * 8 + g;
                int cB = kk + tig * 2;
                uint32_t bh[2], bl[2];
                bh[0] = *(const uint32_t*)&Bsh[bn * PAD + cB];
                bh[1] = *(const uint32_t*)&Bsh[bn * PAD + cB + 8];
                bl[0] = *(const uint32_t*)&Bsl[bn * PAD + cB];
                bl[1] = *(const uint32_t*)&Bsl[bn * PAD + cB + 8];
#pragma unroll
                for (int mt = 0; mt < 2; mt++) {
                    mma16816(acc[mt][nt], ah[mt], bh);
                    mma16816(acc[mt][nt], ah[mt], bl);
                    mma16816(acc[mt][nt], al[mt], bh);
                }
            }
        }
    }

    // epilogue: fp32 out
#pragma unroll
    for (int mt = 0; mt < 2; mt++) {
        int r1 = row0 + wm * 32 + mt * 16 + g;
        int r2 = r1 + 8;
#pragma unroll
        for (int nt = 0; nt < 4; nt++) {
            int cl = wn * 32 + nt * 8 + tig * 2;
            int cg = n0 + cl;
            float b0v = bias[cg], b1v = bias[cg + 1];
            float v00 = acc[mt][nt][0] + b0v, v01 = acc[mt][nt][1] + b1v;
            float v10 = acc[mt][nt][2] + b0v, v11 = acc[mt][nt][3] + b1v;
            if (relu) {
                v00 = fmaxf(v00, 0.f); v01 = fmaxf(v01, 0.f);
                v10 = fmaxf(v10, 0.f); v11 = fmaxf(v11, 0.f);
            }
            if (r1 < NN) *(float2*)&O[(size_t)r1 * ldo + co + cg] = make_float2(v00, v01);
            if (r2 < NN) *(float2*)&O[(size_t)r2 * ldo + co + cg] = make_float2(v10, v11);
        }
    }
}

// ---------------- launch ----------------
extern "C" void kernel_launch(void* const* d_in, const int* in_sizes, int n_in,
                              void* d_out, int out_size) {
    const float* x0  = (const float*)d_in[0];
    const float* x1  = (const float*)d_in[1];
    const void*  eix = d_in[2];
    const float* Wl0 = (const float*)d_in[3];
    const float* Wr0 = (const float*)d_in[4];
    const float* b0  = (const float*)d_in[5];
    const float* Wl1 = (const float*)d_in[6];
    const float* Wr1 = (const float*)d_in[7];
    const float* b1  = (const float*)d_in[8];
    const float* Wlm = (const float*)d_in[9];
    const float* Wrm = (const float*)d_in[10];
    const float* bm  = (const float*)d_in[11];
    const float* Wlo = (const float*)d_in[12];
    const float* Wro = (const float*)d_in[13];
    const float* bo  = (const float*)d_in[14];
    float* out = (float*)d_out;

    cudaFuncSetAttribute(gemm_mma, cudaFuncAttributeMaxDynamicSharedMemorySize, SMEM_SZ);

    float *a0f, *a1f, *hf, *amf, *h2f, *pq, *biasf;
    __nv_bfloat16 *WT0h, *WT0l, *WT1h, *WT1l, *WTmh, *WTml, *WTfh, *WTfl;
    cudaGetSymbolAddress((void**)&a0f, g_a0f);
    cudaGetSymbolAddress((void**)&a1f, g_a1f);
    cudaGetSymbolAddress((void**)&hf,  g_hf);
    cudaGetSymbolAddress((void**)&amf, g_amf);
    cudaGetSymbolAddress((void**)&h2f, g_h2f);
    cudaGetSymbolAddress((void**)&pq,  g_pq);
    cudaGetSymbolAddress((void**)&biasf, g_biasf);
    cudaGetSymbolAddress((void**)&WT0h, g_WT0h); cudaGetSymbolAddress((void**)&WT0l, g_WT0l);
    cudaGetSymbolAddress((void**)&WT1h, g_WT1h); cudaGetSymbolAddress((void**)&WT1l, g_WT1l);
    cudaGetSymbolAddress((void**)&WTmh, g_WTmh); cudaGetSymbolAddress((void**)&WTml, g_WTml);
    cudaGetSymbolAddress((void**)&WTfh, g_WTfh); cudaGetSymbolAddress((void**)&WTfl, g_WTfl);

    // CSR build
    sniff_kernel<<<1, 1>>>((const int*)eix);
    zero_kernel<<<(NN + 255) / 256, 256>>>();
    deg_kernel<<<(EE + 255) / 256, 256>>>(eix);
    scan1_kernel<<<SCANB, 1024>>>();
    scan2_kernel<<<1, 32>>>();
    scan3_kernel<<<SCANB, 1024>>>();
    scatter_kernel<<<(EE + 255) / 256, 256>>>(eix);

    // weight prep (no activation conversion needed anymore)
    wprep_kernel<<<(128 * 256 + 256 * 512 + 255) / 256, 256>>>(Wl0, Wr0, Wl1, Wr1, Wlm, Wrm, Wlo, Wro, bo);

    const int GX = (NN + 127) / 128;  // 391

    // layer 0/1
    agg_xx_kernel<<<NN, 128>>>(x0, x1);
    gemm_mma<<<dim3(GX, 1), 512, SMEM_SZ>>>(a0f, 128, x0, 128, 128, 256,
                                            WT0h, WT0l, b0, 1, hf, 256, 0);
    gemm_mma<<<dim3(GX, 1), 512, SMEM_SZ>>>(a1f, 128, x1, 128, 128, 256,
                                            WT1h, WT1l, b1, 1, hf, 256, 128);

    // middle conv
    agg_mid_kernel<<<NN, 256>>>(hf);
    gemm_mma<<<dim3(GX, 2), 512, SMEM_SZ>>>(amf, 256, hf, 256, 256, 512,
                                            WTmh, WTml, bm, 1, h2f, 256, 0);

    // final conv (project-then-aggregate): pq = h2 @ [Wlo | Wro] + biasf
    gemm_mma<<<dim3(GX, 1), 512, SMEM_SZ>>>(h2f, 256, h2f, 256, 256, 256,
                                            WTfh, WTfl, biasf, 0, pq, 128, 0);
    final_kernel<<<NN, 64>>>(out);
}

// round 9
// speedup vs baseline: 2.8773x; 1.0028x over previous
#include <cuda_runtime.h>
#include <cuda_bf16.h>
#include <cstdint>

constexpr int NN = 50000;
constexpr int EE = 800000;
constexpr int KC = 64;          // K-chunk (elems) per SMEM stage
constexpr int SCANB = 49;       // ceil(NN/1024)

// ---------------- device scratch ----------------
__device__ int   g_is64;
__device__ int   g_deg[NN];
__device__ int   g_cursor[NN];
__device__ int   g_ptr[NN + 1];
__device__ float g_invdeg[NN];
__device__ int   g_edges[EE];
__device__ int   g_part[SCANB];
__device__ int   g_boff[SCANB];

// fp32 activations
__device__ float g_a0f[(size_t)NN * 128];
__device__ float g_a1f[(size_t)NN * 128];
__device__ float g_hf [(size_t)NN * 256];
__device__ float g_amf[(size_t)NN * 256];
__device__ float g_h2f[(size_t)NN * 256];
__device__ float g_pq [(size_t)NN * 128];

// transposed + split weights: WT[n][k] = W[k][n], concat over Ktot
__device__ __nv_bfloat16 g_WT0h[128 * 256];
__device__ __nv_bfloat16 g_WT0l[128 * 256];
__device__ __nv_bfloat16 g_WT1h[128 * 256];
__device__ __nv_bfloat16 g_WT1l[128 * 256];
__device__ __nv_bfloat16 g_WTmh[256 * 512];
__device__ __nv_bfloat16 g_WTml[256 * 512];
__device__ __nv_bfloat16 g_WTfh[128 * 256];
__device__ __nv_bfloat16 g_WTfl[128 * 256];
__device__ float         g_biasf[128];

// ---------------- edge dtype sniff ----------------
__global__ void sniff_kernel(const int* __restrict__ e32) {
    int is64 = 1;
    for (int i = 1; i < 64; i += 2)
        if (e32[i] != 0) { is64 = 0; break; }
    g_is64 = is64;
}
__device__ __forceinline__ int load_edge(const void* e, int idx) {
    if (g_is64) return (int)((const long long*)e)[idx];
    return ((const int*)e)[idx];
}

// ---------------- CSR build ----------------
__global__ void zero_kernel() {
    int i = blockIdx.x * blockDim.x + threadIdx.x;
    if (i < NN) { g_deg[i] = 0; g_cursor[i] = 0; }
}
__global__ void deg_kernel(const void* __restrict__ e) {
    int i = blockIdx.x * blockDim.x + threadIdx.x;
    if (i >= EE) return;
    atomicAdd(&g_deg[load_edge(e, EE + i)], 1);
}
__global__ void scan1_kernel() {
    __shared__ int sm[1024];
    int t = threadIdx.x;
    int i = blockIdx.x * 1024 + t;
    sm[t] = (i < NN) ? g_deg[i] : 0;
    __syncthreads();
    for (int off = 512; off; off >>= 1) {
        if (t < off) sm[t] += sm[t + off];
        __syncthreads();
    }
    if (t == 0) g_part[blockIdx.x] = sm[0];
}
__global__ void scan2_kernel() {
    if (threadIdx.x == 0) {
        int run = 0;
        for (int b = 0; b < SCANB; b++) { g_boff[b] = run; run += g_part[b]; }
        g_ptr[NN] = EE;
    }
}
__global__ void scan3_kernel() {
    __shared__ int sm[1024];
    int t = threadIdx.x;
    int i = blockIdx.x * 1024 + t;
    int v = (i < NN) ? g_deg[i] : 0;
    sm[t] = v;
    __syncthreads();
    for (int off = 1; off < 1024; off <<= 1) {
        int u = (t >= off) ? sm[t - off] : 0;
        __syncthreads();
        if (t >= off) sm[t] += u;
        __syncthreads();
    }
    if (i < NN) {
        g_ptr[i] = g_boff[blockIdx.x] + sm[t] - v;
        g_invdeg[i] = 1.0f / (float)max(v, 1);
    }
}
__global__ void scatter_kernel(const void* __restrict__ e) {
    int i = blockIdx.x * blockDim.x + threadIdx.x;
    if (i >= EE) return;
    int src = load_edge(e, i);
    int dst = load_edge(e, EE + i);
    g_edges[g_ptr[dst] + atomicAdd(&g_cursor[dst], 1)] = src;
}

// ---------------- weight prep ----------------
__device__ __forceinline__ void split2(float v, __nv_bfloat16& h, __nv_bfloat16& l) {
    h = __float2bfloat16(v);
    l = __float2bfloat16(v - __bfloat162float(h));
}
__global__ void wprep_kernel(const float* __restrict__ Wl0, const float* __restrict__ Wr0,
                             const float* __restrict__ Wl1, const float* __restrict__ Wr1,
                             const float* __restrict__ Wlm, const float* __restrict__ Wrm,
                             const float* __restrict__ Wlo, const float* __restrict__ Wro,
                             const float* __restrict__ bo) {
    int i = blockIdx.x * blockDim.x + threadIdx.x;
    if (i < 128 * 256) {
        int n = i >> 8, k = i & 255;
        float w0 = (k < 128) ? Wl0[k * 128 + n] : Wr0[(k - 128) * 128 + n];
        float w1 = (k < 128) ? Wl1[k * 128 + n] : Wr1[(k - 128) * 128 + n];
        split2(w0, g_WT0h[i], g_WT0l[i]);
        split2(w1, g_WT1h[i], g_WT1l[i]);
        float wf = (n < 64) ? Wlo[k * 64 + n] : Wro[k * 64 + (n - 64)];
        split2(wf, g_WTfh[i], g_WTfl[i]);
        if (i < 128) g_biasf[i] = (i < 64) ? 0.f : bo[i - 64];
    }
    int j = i - 128 * 256;
    if (j >= 0 && j < 256 * 512) {
        int n = j >> 9, k = j & 511;
        float w = (k < 256) ? Wlm[k * 256 + n] : Wrm[(k - 256) * 256 + n];
        split2(w, g_WTmh[j], g_WTml[j]);
    }
}

// ---------------- aggregation ----------------
__global__ __launch_bounds__(128) void agg_xx_kernel(
    const float* __restrict__ x0, const float* __restrict__ x1) {
    __shared__ float red0[4][128];
    __shared__ float red1[4][128];
    int node = blockIdx.x;
    int t = threadIdx.x;
    int lane = t & 31, w = t >> 5;
    int s = g_ptr[node], e = g_ptr[node + 1];
    float4 a0 = make_float4(0.f, 0.f, 0.f, 0.f), a1 = a0;
    for (int i = s + w; i < e; i += 4) {
        int src = g_edges[i];
        float4 v0 = __ldg((const float4*)(x0 + (size_t)src * 128) + lane);
        float4 v1 = __ldg((const float4*)(x1 + (size_t)src * 128) + lane);
        a0.x += v0.x; a0.y += v0.y; a0.z += v0.z; a0.w += v0.w;
        a1.x += v1.x; a1.y += v1.y; a1.z += v1.z; a1.w += v1.w;
    }
    *(float4*)&red0[w][lane * 4] = a0;
    *(float4*)&red1[w][lane * 4] = a1;
    __syncthreads();
    float inv = g_invdeg[node];
    float s0 = (red0[0][t] + red0[1][t]) + (red0[2][t] + red0[3][t]);
    float s1 = (red1[0][t] + red1[1][t]) + (red1[2][t] + red1[3][t]);
    g_a0f[(size_t)node * 128 + t] = s0 * inv;
    g_a1f[(size_t)node * 128 + t] = s1 * inv;
}

__global__ __launch_bounds__(256) void agg_mid_kernel(const float* __restrict__ X) {
    __shared__ float red[4][256];
    int node = blockIdx.x;
    int t = threadIdx.x;
    int lane = t & 31, w = t >> 5;
    int el = w >> 1, half = w & 1;
    int s = g_ptr[node], e = g_ptr[node + 1];
    float4 a = make_float4(0.f, 0.f, 0.f, 0.f);
    for (int i = s + el; i < e; i += 4) {
        int src = g_edges[i];
        float4 v = __ldg((const float4*)(X + (size_t)src * 256) + half * 32 + lane);
        a.x += v.x; a.y += v.y; a.z += v.z; a.w += v.w;
    }
    *(float4*)&red[el][half * 128 + lane * 4] = a;
    __syncthreads();
    float sum = (red[0][t] + red[1][t]) + (red[2][t] + red[3][t]);
    g_amf[(size_t)node * 256 + t] = sum * g_invdeg[node];
}

__global__ __launch_bounds__(64) void final_kernel(float* __restrict__ out) {
    __shared__ float red[4][64];
    int node = blockIdx.x;
    int t = threadIdx.x;
    int el = t >> 4, c4 = t & 15;
    int s = g_ptr[node], e = g_ptr[node + 1];
    float4 a = make_float4(0.f, 0.f, 0.f, 0.f);
    for (int i = s + el; i < e; i += 4) {
        int src = g_edges[i];
        float4 v = __ldg((const float4*)(g_pq + (size_t)src * 128) + c4);
        a.x += v.x; a.y += v.y; a.z += v.z; a.w += v.w;
    }
    *(float4*)&red[el][c4 * 4] = a;
    __syncthreads();
    float sum = (red[0][t] + red[1][t]) + (red[2][t] + red[3][t]);
    out[(size_t)node * 64 + t] = sum * g_invdeg[node] + g_pq[(size_t)node * 128 + 64 + t];
}

// ---------------- mma.sync split-bf16 GEMM ----------------
// C[row, n] = sum_k A[row, k] * WT[n, k]; A = (A1|A2) fp32 concat over k.
// fp32 emulated: Ah*Bh + Ah*Bl + Al*Bh, fp32 accumulate.
// 512 threads = 16 warps (4x4); CTA tile 128x128; warp tile 32x32.
// A AND B tiles for chunk c+1 are register-prefetched during chunk c's mma.
// Dual-problem launch: blockIdx.z selects the second parameter set (branch convs).
#define PAD 72
#define AH_OFF 0
#define AL_OFF (128 * PAD * 2)
#define BH_OFF (2 * 128 * PAD * 2)
#define BL_OFF (3 * 128 * PAD * 2)
#define SMEM_SZ (4 * 128 * PAD * 2)

__device__ __forceinline__ void mma16816(float* d, const uint32_t* a, const uint32_t* b) {
    asm volatile(
        "mma.sync.aligned.m16n8k16.row.col.f32.bf16.bf16.f32 "
        "{%0,%1,%2,%3}, {%4,%5,%6,%7}, {%8,%9}, {%0,%1,%2,%3};"
        : "+f"(d[0]), "+f"(d[1]), "+f"(d[2]), "+f"(d[3])
        : "r"(a[0]), "r"(a[1]), "r"(a[2]), "r"(a[3]), "r"(b[0]), "r"(b[1]));
}

__global__ __launch_bounds__(512) void gemm_mma(
    const float* __restrict__ A1a, const float* __restrict__ A2a,
    const __nv_bfloat16* __restrict__ WTha, const __nv_bfloat16* __restrict__ WTla,
    const float* __restrict__ biasa, int coa,
    const float* __restrict__ A1b, const float* __restrict__ A2b,
    const __nv_bfloat16* __restrict__ WThb, const __nv_bfloat16* __restrict__ WTlb,
    const float* __restrict__ biasb, int cob,
    int lda1, int lda2, int K1, int Ktot,
    int relu, float* __restrict__ O, int ldo)
{
    extern __shared__ char smem[];
    __nv_bfloat16* Ash = (__nv_bfloat16*)(smem + AH_OFF);
    __nv_bfloat16* Asl = (__nv_bfloat16*)(smem + AL_OFF);
    __nv_bfloat16* Bsh = (__nv_bfloat16*)(smem + BH_OFF);
    __nv_bfloat16* Bsl = (__nv_bfloat16*)(smem + BL_OFF);

    const float* A1 = A1a; const float* A2 = A2a;
    const __nv_bfloat16* WTh = WTha; const __nv_bfloat16* WTl = WTla;
    const float* bias = biasa; int co = coa;
    if (blockIdx.z) { A1 = A1b; A2 = A2b; WTh = WThb; WTl = WTlb; bias = biasb; co = cob; }

    int tid = threadIdx.x;
    int wid = tid >> 5;
    int lane = tid & 31;
    int g = lane >> 2, tig = lane & 3;
    int wm = wid >> 2, wn = wid & 3;
    int row0 = blockIdx.x * 128;
    int n0 = blockIdx.y * 128;

    const __nv_bfloat16* WThB = WTh + (size_t)n0 * Ktot;
    const __nv_bfloat16* WTlB = WTl + (size_t)n0 * Ktot;

    float acc[2][4][4];
#pragma unroll
    for (int mt = 0; mt < 2; mt++)
#pragma unroll
        for (int nt = 0; nt < 4; nt++)
#pragma unroll
            for (int q = 0; q < 4; q++) acc[mt][nt][q] = 0.f;

    // prefetch registers
    float4 aReg[4];
    uint4  bReg[4];   // [0..1]=hi, [2..3]=lo
    int aRow[4];
#pragma unroll
    for (int it = 0; it < 4; it++) {
        int idx = tid + it * 512;
        aRow[it] = row0 + (idx >> 4);
    }

    auto loadA = [&](int c) {
        int kt = c * KC;
        const float* A; int lda, kb;
        if (kt < K1) { A = A1; lda = lda1; kb = kt; }
        else         { A = A2; lda = lda2; kb = kt - K1; }
#pragma unroll
        for (int it = 0; it < 4; it++) {
            int idx = tid + it * 512;
            int c4 = idx & 15;
            float4 v = make_float4(0.f, 0.f, 0.f, 0.f);
            if (aRow[it] < NN)
                v = __ldg((const float4*)(A + (size_t)aRow[it] * lda + kb) + c4);
            aReg[it] = v;
        }
    };
    auto loadB = [&](int c) {
        int kt = c * KC;
#pragma unroll
        for (int it = 0; it < 2; it++) {
            int idx = tid + it * 512;
            int r = idx >> 3, c8 = idx & 7;
            bReg[it]     = *(const uint4*)(WThB + (size_t)r * Ktot + kt + c8 * 8);
            bReg[it + 2] = *(const uint4*)(WTlB + (size_t)r * Ktot + kt + c8 * 8);
        }
    };

    int nchunks = Ktot / KC;
    loadA(0);
    loadB(0);
    for (int c = 0; c < nchunks; c++) {
        __syncthreads();   // previous chunk's mma done with SMEM
        // store A (split fp32 -> hi/lo bf16)
#pragma unroll
        for (int it = 0; it < 4; it++) {
            int idx = tid + it * 512;
            int r = idx >> 4, c4 = idx & 15;
            float4 v = aReg[it];
            __nv_bfloat162 h01, h23, l01, l23;
            h01.x = __float2bfloat16(v.x); l01.x = __float2bfloat16(v.x - __bfloat162float(h01.x));
            h01.y = __float2bfloat16(v.y); l01.y = __float2bfloat16(v.y - __bfloat162float(h01.y));
            h23.x = __float2bfloat16(v.z); l23.x = __float2bfloat16(v.z - __bfloat162float(h23.x));
            h23.y = __float2bfloat16(v.w); l23.y = __float2bfloat16(v.w - __bfloat162float(h23.y));
            uint2 uh, ul;
            uh.x = *(uint32_t*)&h01; uh.y = *(uint32_t*)&h23;
            ul.x = *(uint32_t*)&l01; ul.y = *(uint32_t*)&l23;
            *(uint2*)&Ash[r * PAD + c4 * 4] = uh;
            *(uint2*)&Asl[r * PAD + c4 * 4] = ul;
        }
        // store B (from prefetch regs)
#pragma unroll
        for (int it = 0; it < 2; it++) {
            int idx = tid + it * 512;
            int r = idx >> 3, c8 = idx & 7;
            *(uint4*)&Bsh[r * PAD + c8 * 8] = bReg[it];
            *(uint4*)&Bsl[r * PAD + c8 * 8] = bReg[it + 2];
        }
        __syncthreads();
        if (c + 1 < nchunks) { loadA(c + 1); loadB(c + 1); }  // overlap with mma

#pragma unroll
        for (int ks = 0; ks < KC / 16; ks++) {
            int kk = ks * 16;
            uint32_t ah[2][4], al[2][4];
#pragma unroll
            for (int mt = 0; mt < 2; mt++) {
                int ar = wm * 32 + mt * 16 + g;
                int cA = kk + tig * 2;
                ah[mt][0] = *(const uint32_t*)&Ash[ar * PAD + cA];
                ah[mt][1] = *(const uint32_t*)&Ash[(ar + 8) * PAD + cA];
                ah[mt][2] = *(const uint32_t*)&Ash[ar * PAD + cA + 8];
                ah[mt][3] = *(const uint32_t*)&Ash[(ar + 8) * PAD + cA + 8];
                al[mt][0] = *(const uint32_t*)&Asl[ar * PAD + cA];
                al[mt][1] = *(const uint32_t*)&Asl[(ar + 8) * PAD + cA];
                al[mt][2] = *(const uint32_t*)&Asl[ar * PAD + cA + 8];
                al[mt][3] = *(const uint32_t*)&Asl[(ar + 8) * PAD + cA + 8];
            }
#pragma unroll
            for (int nt = 0; nt < 4; nt++) {
                int bn = wn * 32 + nt * 8 + g;
                int cB = kk + tig * 2;
                uint32_t bh[2], bl[2];
                bh[0] = *(const uint32_t*)&Bsh[bn * PAD + cB];
                bh[1] = *(const uint32_t*)&Bsh[bn * PAD + cB + 8];
                bl[0] = *(const uint32_t*)&Bsl[bn * PAD + cB];
                bl[1] = *(const uint32_t*)&Bsl[bn * PAD + cB + 8];
#pragma unroll
                for (int mt = 0; mt < 2; mt++) {
                    mma16816(acc[mt][nt], ah[mt], bh);
                    mma16816(acc[mt][nt], ah[mt], bl);
                    mma16816(acc[mt][nt], al[mt], bh);
                }
            }
        }
    }

    // epilogue: fp32 out
#pragma unroll
    for (int mt = 0; mt < 2; mt++) {
        int r1 = row0 + wm * 32 + mt * 16 + g;
        int r2 = r1 + 8;
#pragma unroll
        for (int nt = 0; nt < 4; nt++) {
            int cl = wn * 32 + nt * 8 + tig * 2;
            int cg = n0 + cl;
            float b0v = bias[cg], b1v = bias[cg + 1];
            float v00 = acc[mt][nt][0] + b0v, v01 = acc[mt][nt][1] + b1v;
            float v10 = acc[mt][nt][2] + b0v, v11 = acc[mt][nt][3] + b1v;
            if (relu) {
                v00 = fmaxf(v00, 0.f); v01 = fmaxf(v01, 0.f);
                v10 = fmaxf(v10, 0.f); v11 = fmaxf(v11, 0.f);
            }
            if (r1 < NN) *(float2*)&O[(size_t)r1 * ldo + co + cg] = make_float2(v00, v01);
            if (r2 < NN) *(float2*)&O[(size_t)r2 * ldo + co + cg] = make_float2(v10, v11);
        }
    }
}

// ---------------- launch ----------------
extern "C" void kernel_launch(void* const* d_in, const int* in_sizes, int n_in,
                              void* d_out, int out_size) {
    const float* x0  = (const float*)d_in[0];
    const float* x1  = (const float*)d_in[1];
    const void*  eix = d_in[2];
    const float* Wl0 = (const float*)d_in[3];
    const float* Wr0 = (const float*)d_in[4];
    const float* b0  = (const float*)d_in[5];
    const float* Wl1 = (const float*)d_in[6];
    const float* Wr1 = (const float*)d_in[7];
    const float* b1  = (const float*)d_in[8];
    const float* Wlm = (const float*)d_in[9];
    const float* Wrm = (const float*)d_in[10];
    const float* bm  = (const float*)d_in[11];
    const float* Wlo = (const float*)d_in[12];
    const float* Wro = (const float*)d_in[13];
    const float* bo  = (const float*)d_in[14];
    float* out = (float*)d_out;

    cudaFuncSetAttribute(gemm_mma, cudaFuncAttributeMaxDynamicSharedMemorySize, SMEM_SZ);

    float *a0f, *a1f, *hf, *amf, *h2f, *pq, *biasf;
    __nv_bfloat16 *WT0h, *WT0l, *WT1h, *WT1l, *WTmh, *WTml, *WTfh, *WTfl;
    cudaGetSymbolAddress((void**)&a0f, g_a0f);
    cudaGetSymbolAddress((void**)&a1f, g_a1f);
    cudaGetSymbolAddress((void**)&hf,  g_hf);
    cudaGetSymbolAddress((void**)&amf, g_amf);
    cudaGetSymbolAddress((void**)&h2f, g_h2f);
    cudaGetSymbolAddress((void**)&pq,  g_pq);
    cudaGetSymbolAddress((void**)&biasf, g_biasf);
    cudaGetSymbolAddress((void**)&WT0h, g_WT0h); cudaGetSymbolAddress((void**)&WT0l, g_WT0l);
    cudaGetSymbolAddress((void**)&WT1h, g_WT1h); cudaGetSymbolAddress((void**)&WT1l, g_WT1l);
    cudaGetSymbolAddress((void**)&WTmh, g_WTmh); cudaGetSymbolAddress((void**)&WTml, g_WTml);
    cudaGetSymbolAddress((void**)&WTfh, g_WTfh); cudaGetSymbolAddress((void**)&WTfl, g_WTfl);

    // CSR build
    sniff_kernel<<<1, 1>>>((const int*)eix);
    zero_kernel<<<(NN + 255) / 256, 256>>>();
    deg_kernel<<<(EE + 255) / 256, 256>>>(eix);
    scan1_kernel<<<SCANB, 1024>>>();
    scan2_kernel<<<1, 32>>>();
    scan3_kernel<<<SCANB, 1024>>>();
    scatter_kernel<<<(EE + 255) / 256, 256>>>(eix);

    // weight prep
    wprep_kernel<<<(128 * 256 + 256 * 512 + 255) / 256, 256>>>(Wl0, Wr0, Wl1, Wr1, Wlm, Wrm, Wlo, Wro, bo);

    const int GX = (NN + 127) / 128;  // 391

    // layer 0 + 1 fused into one launch (z selects branch)
    agg_xx_kernel<<<NN, 128>>>(x0, x1);
    gemm_mma<<<dim3(GX, 1, 2), 512, SMEM_SZ>>>(
        a0f, x0, WT0h, WT0l, b0, 0,
        a1f, x1, WT1h, WT1l, b1, 128,
        128, 128, 128, 256, 1, hf, 256);

    // middle conv
    agg_mid_kernel<<<NN, 256>>>(hf);
    gemm_mma<<<dim3(GX, 2, 1), 512, SMEM_SZ>>>(
        amf, hf, WTmh, WTml, bm, 0,
        amf, hf, WTmh, WTml, bm, 0,
        256, 256, 256, 512, 1, h2f, 256);

    // final conv (project-then-aggregate): pq = h2 @ [Wlo | Wro] + biasf
    gemm_mma<<<dim3(GX, 1, 1), 512, SMEM_SZ>>>(
        h2f, h2f, WTfh, WTfl, biasf, 0,
        h2f, h2f, WTfh, WTfl, biasf, 0,
        256, 256, 256, 256, 0, pq, 128);
    final_kernel<<<NN, 64>>>(out);
}